// round 3
// baseline (speedup 1.0000x reference)
#include <cuda_runtime.h>
#include <cuda_bf16.h>
#include <cstdint>

// ---------------------------------------------------------------------------
// Problem constants
// ---------------------------------------------------------------------------
#define NROWS 2048
#define NFEAT 128
#define TILE  128
#define PREP_BLOCKS 128           // 16 rows per block

// ---------------------------------------------------------------------------
// Device scratch (no allocation allowed)
// ---------------------------------------------------------------------------
__device__ __nv_bfloat16 g_Xb[NROWS * NFEAT];        // bf16-quantized X
__device__ float g_norm[NROWS];                      // row norms of quantized X
__device__ float g_s_part[PREP_BLOCKS][NFEAT];       // per-block feature-sum partials
__device__ float g_sumn_part[PREP_BLOCKS];           // per-block sum-of-norms partials
__device__ float g_c;                                // inv2s * log2(e)
__device__ int   g_ctr;                              // last-block counter (reset each run)

// ---------------------------------------------------------------------------
// Helpers
// ---------------------------------------------------------------------------
__device__ __forceinline__ uint32_t smem_to_u32(const void* p) {
    uint32_t a;
    asm("{ .reg .u64 t; cvta.to.shared.u64 t, %1; cvt.u32.u64 %0, t; }" : "=r"(a) : "l"(p));
    return a;
}

__device__ __forceinline__ void ldmatrix_x4(uint32_t& r0, uint32_t& r1,
                                            uint32_t& r2, uint32_t& r3, uint32_t addr) {
    asm volatile("ldmatrix.sync.aligned.m8n8.x4.shared.b16 {%0,%1,%2,%3}, [%4];"
                 : "=r"(r0), "=r"(r1), "=r"(r2), "=r"(r3) : "r"(addr));
}

__device__ __forceinline__ void mma_16816(float* d, const uint32_t* a, const uint32_t* b) {
    asm volatile(
        "mma.sync.aligned.m16n8k16.row.col.f32.bf16.bf16.f32 "
        "{%0,%1,%2,%3}, {%4,%5,%6,%7}, {%8,%9}, {%0,%1,%2,%3};"
        : "+f"(d[0]), "+f"(d[1]), "+f"(d[2]), "+f"(d[3])
        : "r"(a[0]), "r"(a[1]), "r"(a[2]), "r"(a[3]), "r"(b[0]), "r"(b[1]));
}

__device__ __forceinline__ float ex2f(float x) {
    float r;
    asm("ex2.approx.ftz.f32 %0, %1;" : "=f"(r) : "f"(x));
    return r;
}

// ---------------------------------------------------------------------------
// Kernel 1: quantize + norms + feature-sum partials + last-block sigma finalize.
// grid PREP_BLOCKS, block 256 (8 warps). Block handles 16 rows: warp w rows
// rb + 2w, rb + 2w + 1; lane handles one float4 (4 features) per row.
// ---------------------------------------------------------------------------
__global__ void __launch_bounds__(256) prep_kernel(const float* __restrict__ X) {
    int b   = blockIdx.x;
    int tid = threadIdx.x;
    int wid = tid >> 5;
    int lid = tid & 31;
    int rb  = b * 16;

    __shared__ float ss[8][NFEAT];
    __shared__ float sn[8];
    __shared__ int   s_last;

    float s0 = 0.f, s1 = 0.f, s2 = 0.f, s3 = 0.f;
    float wn = 0.f;

    #pragma unroll
    for (int r = 0; r < 2; r++) {
        int row = rb + wid * 2 + r;
        float4 v = reinterpret_cast<const float4*>(X + (size_t)row * NFEAT)[lid];
        __nv_bfloat16 b0 = __float2bfloat16(v.x);
        __nv_bfloat16 b1 = __float2bfloat16(v.y);
        __nv_bfloat16 b2 = __float2bfloat16(v.z);
        __nv_bfloat16 b3 = __float2bfloat16(v.w);
        __nv_bfloat162* dst =
            reinterpret_cast<__nv_bfloat162*>(g_Xb + (size_t)row * NFEAT) + lid * 2;
        dst[0] = __nv_bfloat162(b0, b1);
        dst[1] = __nv_bfloat162(b2, b3);
        // quantized values downstream (diag exactly 0 -> out = 1)
        float fx = __bfloat162float(b0), fy = __bfloat162float(b1);
        float fz = __bfloat162float(b2), fw = __bfloat162float(b3);
        float sq = fx * fx + fy * fy + fz * fz + fw * fw;
        #pragma unroll
        for (int o = 16; o > 0; o >>= 1) sq += __shfl_xor_sync(0xFFFFFFFFu, sq, o);
        if (lid == 0) { g_norm[row] = sq; wn += sq; }
        s0 += fx; s1 += fy; s2 += fz; s3 += fw;
    }
    ss[wid][lid * 4 + 0] = s0;
    ss[wid][lid * 4 + 1] = s1;
    ss[wid][lid * 4 + 2] = s2;
    ss[wid][lid * 4 + 3] = s3;
    if (lid == 0) sn[wid] = wn;
    __syncthreads();
    if (tid < NFEAT) {
        float t = 0.f;
        #pragma unroll
        for (int w = 0; w < 8; w++) t += ss[w][tid];
        g_s_part[b][tid] = t;
    }
    if (tid == 0) {
        float t = 0.f;
        #pragma unroll
        for (int w = 0; w < 8; w++) t += sn[w];
        g_sumn_part[b] = t;
    }

    // ---- last-block sigma finalize (saves a kernel launch) ----
    __threadfence();
    __syncthreads();
    if (tid == 0) s_last = (atomicAdd(&g_ctr, 1) == PREP_BLOCKS - 1) ? 1 : 0;
    __syncthreads();
    if (!s_last) return;

    // This block is last: all partials are globally visible.
    __shared__ float red[4];
    if (tid < NFEAT) {
        float sf = 0.f;
        #pragma unroll 4
        for (int p = 0; p < PREP_BLOCKS; p++) sf += __ldcg(&g_s_part[p][tid]);
        float v = sf * sf;
        #pragma unroll
        for (int o = 16; o > 0; o >>= 1) v += __shfl_xor_sync(0xFFFFFFFFu, v, o);
        if (lid == 0) red[wid] = v;
    }
    __syncthreads();
    if (tid == 0) {
        float S2 = red[0] + red[1] + red[2] + red[3];
        float sumn = 0.f;
        #pragma unroll 4
        for (int p = 0; p < PREP_BLOCKS; p++) sumn += __ldcg(&g_sumn_part[p]);
        float Nf = (float)NROWS;
        // sigma^2 = (2N*sumn - 2*S2)/N^2 ; inv2s = 1/(2 sigma^2)
        float inv2s = (Nf * Nf) / (4.f * Nf * sumn - 4.f * S2);
        g_c = inv2s * 1.4426950408889634f;   // fold log2(e): use ex2 in epilogue
        g_ctr = 0;                           // reset for next graph replay
    }
}

// ---------------------------------------------------------------------------
// Kernel 2: main. grid (16,16), 256 threads (8 warps), 2 CTAs/SM => single wave.
// CTA computes a 128x128 output tile via ldmatrix + mma.sync bf16.
// Smem: ci/cj constant tiles + A,B bf16 tiles (256B/row, chunk-XOR swizzle).
// Epilogue: out = ex2(dot * 2c + ci + cj), ci = -ni*c, cj = -nj*c.
// ---------------------------------------------------------------------------
#define OFF_CI  0
#define OFF_CJ  512
#define OFF_A   1024
#define OFF_B   (1024 + 32768)
#define SMEM_TOTAL (OFF_B + 32768)

__global__ void __launch_bounds__(256, 2) gauss_main_kernel(float* __restrict__ out) {
    extern __shared__ char smem[];
    uint32_t sb = smem_to_u32(smem);
    int tid = threadIdx.x;
    int wid = tid >> 5;
    int lid = tid & 31;
    int bj  = blockIdx.x;
    int bi  = blockIdx.y;

    float c = g_c;

    // constant tiles: ci for A rows, cj for B rows
    if (tid < TILE)
        reinterpret_cast<float*>(smem + OFF_CI)[tid] = -g_norm[bi * TILE + tid] * c;
    else
        reinterpret_cast<float*>(smem + OFF_CJ)[tid - TILE] =
            -g_norm[bj * TILE + (tid - TILE)] * c;

    // ---- load A/B tiles into swizzled smem ----
    const uint4* A4 = reinterpret_cast<const uint4*>(g_Xb + (size_t)bi * TILE * NFEAT);
    const uint4* B4 = reinterpret_cast<const uint4*>(g_Xb + (size_t)bj * TILE * NFEAT);
    #pragma unroll
    for (int idx = tid; idx < 2048; idx += 256) {
        int row = idx >> 4;
        int ch  = idx & 15;
        uint32_t off = (uint32_t)row * 256u + (uint32_t)(ch ^ (row & 7)) * 16u;
        *reinterpret_cast<uint4*>(smem + OFF_A + off) = A4[idx];
        *reinterpret_cast<uint4*>(smem + OFF_B + off) = B4[idx];
    }
    __syncthreads();

    // ---- per-warp MMA: warp computes rows wm..wm+31, cols wn..wn+63 ----
    int wm = (wid & 3) * 32;
    int wn = (wid >> 2) * 64;

    float d[2][8][4];
    #pragma unroll
    for (int mt = 0; mt < 2; mt++)
        #pragma unroll
        for (int nt = 0; nt < 8; nt++)
            #pragma unroll
            for (int e = 0; e < 4; e++) d[mt][nt][e] = 0.f;

    uint32_t a_row  = (uint32_t)(wm + (lid & 15));
    uint32_t a_cbit = (uint32_t)(lid >> 4);
    uint32_t a_rl   = a_row & 7;
    uint32_t a_base0 = sb + OFF_A + a_row * 256u;
    uint32_t a_base1 = a_base0 + 16u * 256u;

    uint32_t b_row  = (uint32_t)(wn + (lid & 7) + ((lid & 16) >> 1));
    uint32_t b_cbit = (uint32_t)((lid >> 3) & 1);
    uint32_t b_rl   = b_row & 7;
    uint32_t b_base = sb + OFF_B + b_row * 256u;

    #pragma unroll
    for (int kc = 0; kc < 8; kc++) {
        uint32_t a[2][4];
        {
            uint32_t sc = ((uint32_t)(2 * kc) + a_cbit) ^ a_rl;
            ldmatrix_x4(a[0][0], a[0][1], a[0][2], a[0][3], a_base0 + (sc << 4));
            ldmatrix_x4(a[1][0], a[1][1], a[1][2], a[1][3], a_base1 + (sc << 4));
        }
        uint32_t b[8][2];
        #pragma unroll
        for (int p = 0; p < 4; p++) {
            uint32_t sc = ((uint32_t)(2 * kc) + b_cbit) ^ b_rl;
            uint32_t addr = b_base + (uint32_t)p * (16u * 256u) + (sc << 4);
            ldmatrix_x4(b[2 * p][0], b[2 * p][1], b[2 * p + 1][0], b[2 * p + 1][1], addr);
        }
        #pragma unroll
        for (int mt = 0; mt < 2; mt++)
            #pragma unroll
            for (int nt = 0; nt < 8; nt++)
                mma_16816(d[mt][nt], a[mt], b[nt]);
    }

    // ---- epilogue: ex2(dot * 2c + ci + cj) ----
    float sc2 = 2.f * c;
    const float* cis = reinterpret_cast<const float*>(smem + OFF_CI);
    const float* cjs = reinterpret_cast<const float*>(smem + OFF_CJ);
    int quad = lid >> 2;
    int qt   = lid & 3;

    #pragma unroll
    for (int mt = 0; mt < 2; mt++) {
        #pragma unroll
        for (int half = 0; half < 2; half++) {
            int r  = wm + mt * 16 + quad + half * 8;
            float ci = cis[r];
            float* orow = out + (size_t)(bi * TILE + r) * NROWS + (size_t)bj * TILE + wn;
            #pragma unroll
            for (int nt = 0; nt < 8; nt++) {
                int col = nt * 8 + qt * 2;
                float c0 = ci + cjs[wn + col];
                float c1 = ci + cjs[wn + col + 1];
                float e0 = fmaf(d[mt][nt][half * 2 + 0], sc2, c0);
                float e1 = fmaf(d[mt][nt][half * 2 + 1], sc2, c1);
                float2 o = make_float2(ex2f(e0), ex2f(e1));
                *reinterpret_cast<float2*>(orow + col) = o;
            }
        }
    }
}

// ---------------------------------------------------------------------------
// Launch
// ---------------------------------------------------------------------------
extern "C" void kernel_launch(void* const* d_in, const int* in_sizes, int n_in,
                              void* d_out, int out_size) {
    const float* X = (const float*)d_in[0];
    float* out = (float*)d_out;
    (void)in_sizes; (void)n_in; (void)out_size;

    cudaFuncSetAttribute(gauss_main_kernel,
                         cudaFuncAttributeMaxDynamicSharedMemorySize, SMEM_TOTAL);

    prep_kernel<<<PREP_BLOCKS, 256>>>(X);
    gauss_main_kernel<<<dim3(16, 16), 256, SMEM_TOTAL>>>(out);
}

// round 4
// speedup vs baseline: 1.1875x; 1.1875x over previous
#include <cuda_runtime.h>
#include <cuda_bf16.h>
#include <cstdint>

// ---------------------------------------------------------------------------
// Problem constants
// ---------------------------------------------------------------------------
#define NROWS 2048
#define NFEAT 128
#define TILE  128
#define PREP_BLOCKS 128           // 16 rows per block

// ---------------------------------------------------------------------------
// Device scratch (no allocation allowed)
// ---------------------------------------------------------------------------
__device__ __nv_bfloat16 g_Xb[NROWS * NFEAT];        // bf16-quantized X
__device__ float g_norm[NROWS];                      // row norms of quantized X
__device__ float g_s_part[PREP_BLOCKS][NFEAT];       // per-block feature-sum partials
__device__ float g_sumn_part[PREP_BLOCKS];           // per-block sum-of-norms partials
__device__ float g_c;                                // inv2s * log2(e)
__device__ int   g_ctr;                              // last-block counter (reset each run)

// ---------------------------------------------------------------------------
// Helpers
// ---------------------------------------------------------------------------
__device__ __forceinline__ uint32_t smem_to_u32(const void* p) {
    uint32_t a;
    asm("{ .reg .u64 t; cvta.to.shared.u64 t, %1; cvt.u32.u64 %0, t; }" : "=r"(a) : "l"(p));
    return a;
}

__device__ __forceinline__ void ldmatrix_x4(uint32_t& r0, uint32_t& r1,
                                            uint32_t& r2, uint32_t& r3, uint32_t addr) {
    asm volatile("ldmatrix.sync.aligned.m8n8.x4.shared.b16 {%0,%1,%2,%3}, [%4];"
                 : "=r"(r0), "=r"(r1), "=r"(r2), "=r"(r3) : "r"(addr));
}

__device__ __forceinline__ void mma_16816(float* d, const uint32_t* a, const uint32_t* b) {
    asm volatile(
        "mma.sync.aligned.m16n8k16.row.col.f32.bf16.bf16.f32 "
        "{%0,%1,%2,%3}, {%4,%5,%6,%7}, {%8,%9}, {%0,%1,%2,%3};"
        : "+f"(d[0]), "+f"(d[1]), "+f"(d[2]), "+f"(d[3])
        : "r"(a[0]), "r"(a[1]), "r"(a[2]), "r"(a[3]), "r"(b[0]), "r"(b[1]));
}

__device__ __forceinline__ float ex2f(float x) {
    float r;
    asm("ex2.approx.ftz.f32 %0, %1;" : "=f"(r) : "f"(x));
    return r;
}

// ---------------------------------------------------------------------------
// Kernel 1: quantize + norms + feature-sum partials + last-block sigma finalize.
// grid PREP_BLOCKS, block 256 (8 warps). Block handles 16 rows.
// Finalize is parallelized for MLP: 256 threads x 64 partials (unroll 16).
// ---------------------------------------------------------------------------
__global__ void __launch_bounds__(256) prep_kernel(const float* __restrict__ X) {
    int b   = blockIdx.x;
    int tid = threadIdx.x;
    int wid = tid >> 5;
    int lid = tid & 31;
    int rb  = b * 16;

    __shared__ float ss[8][NFEAT];
    __shared__ float sn[8];
    __shared__ int   s_last;

    float s0 = 0.f, s1 = 0.f, s2 = 0.f, s3 = 0.f;
    float wn = 0.f;

    #pragma unroll
    for (int r = 0; r < 2; r++) {
        int row = rb + wid * 2 + r;
        float4 v = reinterpret_cast<const float4*>(X + (size_t)row * NFEAT)[lid];
        __nv_bfloat16 b0 = __float2bfloat16(v.x);
        __nv_bfloat16 b1 = __float2bfloat16(v.y);
        __nv_bfloat16 b2 = __float2bfloat16(v.z);
        __nv_bfloat16 b3 = __float2bfloat16(v.w);
        __nv_bfloat162* dst =
            reinterpret_cast<__nv_bfloat162*>(g_Xb + (size_t)row * NFEAT) + lid * 2;
        dst[0] = __nv_bfloat162(b0, b1);
        dst[1] = __nv_bfloat162(b2, b3);
        // quantized values downstream (diag exactly 0 -> out = 1)
        float fx = __bfloat162float(b0), fy = __bfloat162float(b1);
        float fz = __bfloat162float(b2), fw = __bfloat162float(b3);
        float sq = fx * fx + fy * fy + fz * fz + fw * fw;
        #pragma unroll
        for (int o = 16; o > 0; o >>= 1) sq += __shfl_xor_sync(0xFFFFFFFFu, sq, o);
        if (lid == 0) { g_norm[row] = sq; wn += sq; }
        s0 += fx; s1 += fy; s2 += fz; s3 += fw;
    }
    ss[wid][lid * 4 + 0] = s0;
    ss[wid][lid * 4 + 1] = s1;
    ss[wid][lid * 4 + 2] = s2;
    ss[wid][lid * 4 + 3] = s3;
    if (lid == 0) sn[wid] = wn;
    __syncthreads();
    if (tid < NFEAT) {
        float t = 0.f;
        #pragma unroll
        for (int w = 0; w < 8; w++) t += ss[w][tid];
        g_s_part[b][tid] = t;
    }
    if (tid == 0) {
        float t = 0.f;
        #pragma unroll
        for (int w = 0; w < 8; w++) t += sn[w];
        g_sumn_part[b] = t;
    }

    // ---- last-block sigma finalize ----
    __threadfence();
    __syncthreads();
    if (tid == 0) s_last = (atomicAdd(&g_ctr, 1) == PREP_BLOCKS - 1) ? 1 : 0;
    __syncthreads();
    if (!s_last) return;

    // All partials globally visible. High-MLP parallel reduction.
    __shared__ float ssf[2][NFEAT];
    __shared__ float red[5];
    {
        int f = tid & 127;
        int g = tid >> 7;              // 0 or 1
        float sf = 0.f;
        #pragma unroll 16
        for (int p = g * 64; p < g * 64 + 64; p++) sf += __ldcg(&g_s_part[p][f]);
        ssf[g][f] = sf;
    }
    if (tid < 32) {
        float sna = 0.f;
        #pragma unroll
        for (int q = 0; q < 4; q++) sna += __ldcg(&g_sumn_part[tid * 4 + q]);
        #pragma unroll
        for (int o = 16; o > 0; o >>= 1) sna += __shfl_xor_sync(0xFFFFFFFFu, sna, o);
        if (tid == 0) red[4] = sna;
    }
    __syncthreads();
    if (tid < NFEAT) {
        float s = ssf[0][tid] + ssf[1][tid];
        float v = s * s;
        #pragma unroll
        for (int o = 16; o > 0; o >>= 1) v += __shfl_xor_sync(0xFFFFFFFFu, v, o);
        if (lid == 0) red[wid] = v;
    }
    __syncthreads();
    if (tid == 0) {
        float S2   = red[0] + red[1] + red[2] + red[3];
        float sumn = red[4];
        float Nf = (float)NROWS;
        // inv2s = 1/(2 sigma^2), sigma^2 = (2N*sumn - 2*S2)/N^2
        float inv2s = (Nf * Nf) / (4.f * Nf * sumn - 4.f * S2);
        g_c = inv2s * 1.4426950408889634f;   // fold log2(e) for ex2
        g_ctr = 0;                           // reset for next graph replay
    }
}

// ---------------------------------------------------------------------------
// Kernel 2: main. grid (16,16), 256 threads, 2 CTAs/SM.
// SYMMETRY: only bi <= bj CTAs compute (136 work, 120 exit). Off-diagonal
// CTAs store their tile from registers AND the transposed tile via a
// 132-padded f32 smem staging buffer (reusing A/B tile smem after barrier).
// Epilogue: out = ex2(dot * 2c + ci + cj), ci = -ni*c, cj = -nj*c.
// ---------------------------------------------------------------------------
#define OFF_CI  0
#define OFF_CJ  512
#define OFF_A   1024
#define OFF_B   (1024 + 32768)
#define STAGE_PAD 132                         // words per staged row
#define SMEM_TOTAL (1024 + 128 * STAGE_PAD * 4)   // 68608 >= 1024+65536

__global__ void __launch_bounds__(256, 2) gauss_main_kernel(float* __restrict__ out) {
    extern __shared__ char smem[];
    uint32_t sb = smem_to_u32(smem);
    int tid = threadIdx.x;
    int wid = tid >> 5;
    int lid = tid & 31;
    int bj  = blockIdx.x;
    int bi  = blockIdx.y;

    if (bi > bj) return;                      // symmetry: lower triangle skipped
    bool offdiag = (bi != bj);

    float c = g_c;

    // constant tiles: ci for A rows, cj for B rows
    if (tid < TILE)
        reinterpret_cast<float*>(smem + OFF_CI)[tid] = -g_norm[bi * TILE + tid] * c;
    else
        reinterpret_cast<float*>(smem + OFF_CJ)[tid - TILE] =
            -g_norm[bj * TILE + (tid - TILE)] * c;

    // ---- load A/B tiles into swizzled smem ----
    const uint4* A4 = reinterpret_cast<const uint4*>(g_Xb + (size_t)bi * TILE * NFEAT);
    const uint4* B4 = reinterpret_cast<const uint4*>(g_Xb + (size_t)bj * TILE * NFEAT);
    #pragma unroll
    for (int idx = tid; idx < 2048; idx += 256) {
        int row = idx >> 4;
        int ch  = idx & 15;
        uint32_t off = (uint32_t)row * 256u + (uint32_t)(ch ^ (row & 7)) * 16u;
        *reinterpret_cast<uint4*>(smem + OFF_A + off) = A4[idx];
        *reinterpret_cast<uint4*>(smem + OFF_B + off) = B4[idx];
    }
    __syncthreads();

    // ---- per-warp MMA: warp computes rows wm..wm+31, cols wn..wn+63 ----
    int wm = (wid & 3) * 32;
    int wn = (wid >> 2) * 64;

    float d[2][8][4];
    #pragma unroll
    for (int mt = 0; mt < 2; mt++)
        #pragma unroll
        for (int nt = 0; nt < 8; nt++)
            #pragma unroll
            for (int e = 0; e < 4; e++) d[mt][nt][e] = 0.f;

    uint32_t a_row  = (uint32_t)(wm + (lid & 15));
    uint32_t a_cbit = (uint32_t)(lid >> 4);
    uint32_t a_rl   = a_row & 7;
    uint32_t a_base0 = sb + OFF_A + a_row * 256u;
    uint32_t a_base1 = a_base0 + 16u * 256u;

    uint32_t b_row  = (uint32_t)(wn + (lid & 7) + ((lid & 16) >> 1));
    uint32_t b_cbit = (uint32_t)((lid >> 3) & 1);
    uint32_t b_rl   = b_row & 7;
    uint32_t b_base = sb + OFF_B + b_row * 256u;

    #pragma unroll
    for (int kc = 0; kc < 8; kc++) {
        uint32_t a[2][4];
        {
            uint32_t sc = ((uint32_t)(2 * kc) + a_cbit) ^ a_rl;
            ldmatrix_x4(a[0][0], a[0][1], a[0][2], a[0][3], a_base0 + (sc << 4));
            ldmatrix_x4(a[1][0], a[1][1], a[1][2], a[1][3], a_base1 + (sc << 4));
        }
        uint32_t b[8][2];
        #pragma unroll
        for (int p = 0; p < 4; p++) {
            uint32_t sc = ((uint32_t)(2 * kc) + b_cbit) ^ b_rl;
            uint32_t addr = b_base + (uint32_t)p * (16u * 256u) + (sc << 4);
            ldmatrix_x4(b[2 * p][0], b[2 * p][1], b[2 * p + 1][0], b[2 * p + 1][1], addr);
        }
        #pragma unroll
        for (int mt = 0; mt < 2; mt++)
            #pragma unroll
            for (int nt = 0; nt < 8; nt++)
                mma_16816(d[mt][nt], a[mt], b[nt]);
    }

    // ---- epilogue pass 1: compute o in place, direct stores ----
    float sc2 = 2.f * c;
    const float* cis = reinterpret_cast<const float*>(smem + OFF_CI);
    const float* cjs = reinterpret_cast<const float*>(smem + OFF_CJ);
    int quad = lid >> 2;
    int qt   = lid & 3;

    #pragma unroll
    for (int mt = 0; mt < 2; mt++) {
        #pragma unroll
        for (int half = 0; half < 2; half++) {
            int r  = wm + mt * 16 + quad + half * 8;
            float ci = cis[r];
            float* orow = out + (size_t)(bi * TILE + r) * NROWS + (size_t)bj * TILE + wn;
            #pragma unroll
            for (int nt = 0; nt < 8; nt++) {
                int col = nt * 8 + qt * 2;
                float e0 = fmaf(d[mt][nt][half * 2 + 0], sc2, ci + cjs[wn + col]);
                float e1 = fmaf(d[mt][nt][half * 2 + 1], sc2, ci + cjs[wn + col + 1]);
                float o0 = ex2f(e0);
                float o1 = ex2f(e1);
                d[mt][nt][half * 2 + 0] = o0;     // keep for transpose pass
                d[mt][nt][half * 2 + 1] = o1;
                *reinterpret_cast<float2*>(orow + col) = make_float2(o0, o1);
            }
        }
    }

    if (!offdiag) return;   // uniform per block

    // ---- pass 2: stage transposed tile in smem (overwrites A/B tiles) ----
    __syncthreads();        // all warps done reading A/B smem
    float* stage = reinterpret_cast<float*>(smem + OFF_A);
    #pragma unroll
    for (int mt = 0; mt < 2; mt++) {
        #pragma unroll
        for (int half = 0; half < 2; half++) {
            int r = wm + mt * 16 + quad + half * 8;
            #pragma unroll
            for (int nt = 0; nt < 8; nt++) {
                int cc = wn + nt * 8 + qt * 2;
                // transposed layout: stage[c][r], conflict-free (bank = 4qt+quad)
                stage[(uint32_t)cc * STAGE_PAD + r]       = d[mt][nt][half * 2 + 0];
                stage[(uint32_t)(cc + 1) * STAGE_PAD + r] = d[mt][nt][half * 2 + 1];
            }
        }
    }
    __syncthreads();

    // ---- pass 3: contiguous reads of transposed rows -> float4 stores ----
    {
        int ct = tid >> 1;                    // transposed row (= tile col)
        int rh = (tid & 1) * 64;              // half of the 128 r-values
        const float* srow = stage + (uint32_t)ct * STAGE_PAD + rh;
        float* drow = out + (size_t)(bj * TILE + ct) * NROWS + (size_t)bi * TILE + rh;
        #pragma unroll
        for (int q = 0; q < 16; q++) {
            float4 v = *reinterpret_cast<const float4*>(srow + q * 4);
            *reinterpret_cast<float4*>(drow + q * 4) = v;
        }
    }
}

// ---------------------------------------------------------------------------
// Launch
// ---------------------------------------------------------------------------
extern "C" void kernel_launch(void* const* d_in, const int* in_sizes, int n_in,
                              void* d_out, int out_size) {
    const float* X = (const float*)d_in[0];
    float* out = (float*)d_out;
    (void)in_sizes; (void)n_in; (void)out_size;

    cudaFuncSetAttribute(gauss_main_kernel,
                         cudaFuncAttributeMaxDynamicSharedMemorySize, SMEM_TOTAL);

    prep_kernel<<<PREP_BLOCKS, 256>>>(X);
    gauss_main_kernel<<<dim3(16, 16), 256, SMEM_TOTAL>>>(out);
}

// round 5
// speedup vs baseline: 1.5133x; 1.2743x over previous
#include <cuda_runtime.h>
#include <cuda_bf16.h>
#include <cstdint>

// ---------------------------------------------------------------------------
// Problem constants
// ---------------------------------------------------------------------------
#define NROWS 2048
#define NFEAT 128
#define TILE  128
#define GRID  256                 // 16x16 tiles, one CTA each; all co-resident

// ---------------------------------------------------------------------------
// Device scratch (zero-initialized; no allocation allowed)
// ---------------------------------------------------------------------------
__device__ __nv_bfloat16 g_Xb[NROWS * NFEAT];   // bf16-quantized X
__device__ float g_norm[NROWS];                 // row norms of quantized X
__device__ float g_s_part[GRID][NFEAT];         // per-CTA feature-sum partials
__device__ float g_sumn_part[GRID];             // per-CTA sum-of-norms partials
__device__ float g_c;                           // inv2s * log2(e)
__device__ int   g_ctr;                         // phase-1 arrive counter
__device__ int   g_ctr2;                        // exit counter (for reset)
__device__ int   g_flag;                        // sigma-ready flag

// ---------------------------------------------------------------------------
// Helpers
// ---------------------------------------------------------------------------
__device__ __forceinline__ uint32_t smem_to_u32(const void* p) {
    uint32_t a;
    asm("{ .reg .u64 t; cvta.to.shared.u64 t, %1; cvt.u32.u64 %0, t; }" : "=r"(a) : "l"(p));
    return a;
}

__device__ __forceinline__ void ldmatrix_x4(uint32_t& r0, uint32_t& r1,
                                            uint32_t& r2, uint32_t& r3, uint32_t addr) {
    asm volatile("ldmatrix.sync.aligned.m8n8.x4.shared.b16 {%0,%1,%2,%3}, [%4];"
                 : "=r"(r0), "=r"(r1), "=r"(r2), "=r"(r3) : "r"(addr));
}

__device__ __forceinline__ void mma_16816(float* d, const uint32_t* a, const uint32_t* b) {
    asm volatile(
        "mma.sync.aligned.m16n8k16.row.col.f32.bf16.bf16.f32 "
        "{%0,%1,%2,%3}, {%4,%5,%6,%7}, {%8,%9}, {%0,%1,%2,%3};"
        : "+f"(d[0]), "+f"(d[1]), "+f"(d[2]), "+f"(d[3])
        : "r"(a[0]), "r"(a[1]), "r"(a[2]), "r"(a[3]), "r"(b[0]), "r"(b[1]));
}

__device__ __forceinline__ float ex2f(float x) {
    float r;
    asm("ex2.approx.ftz.f32 %0, %1;" : "=f"(r) : "f"(x));
    return r;
}

// ---------------------------------------------------------------------------
// Smem layout (dynamic, 66560 B): ci/cj tiles + A/B bf16 tiles.
// OFF_A region is reused: phase-1 feature partials, finalize scratch, tiles.
// ---------------------------------------------------------------------------
#define OFF_CI  0
#define OFF_CJ  512
#define OFF_A   1024
#define OFF_B   (1024 + 32768)
#define SMEM_TOTAL (OFF_B + 32768)

// ---------------------------------------------------------------------------
// ONE fused kernel: prep -> device barrier + sigma -> GEMM + exp epilogue.
// grid 256 CTAs, 256 threads, 2 CTAs/SM guaranteed => all resident (spin-safe).
// ---------------------------------------------------------------------------
__global__ void __launch_bounds__(256, 2) gauss_fused_kernel(
        const float* __restrict__ X, float* __restrict__ out) {
    extern __shared__ char smem[];
    uint32_t sb = smem_to_u32(smem);
    int b   = blockIdx.x;
    int tid = threadIdx.x;
    int wid = tid >> 5;
    int lid = tid & 31;

    __shared__ float sn[8];
    __shared__ float red[5];
    __shared__ int   s_last;

    // =============== Phase 1: quantize 8 rows, partials ===============
    {
        float* ss = reinterpret_cast<float*>(smem + OFF_A);   // [8][128]
        int row = b * 8 + wid;                                // warp owns one row
        float4 v = reinterpret_cast<const float4*>(X + (size_t)row * NFEAT)[lid];
        __nv_bfloat16 b0 = __float2bfloat16(v.x);
        __nv_bfloat16 b1 = __float2bfloat16(v.y);
        __nv_bfloat16 b2 = __float2bfloat16(v.z);
        __nv_bfloat16 b3 = __float2bfloat16(v.w);
        __nv_bfloat162* dst =
            reinterpret_cast<__nv_bfloat162*>(g_Xb + (size_t)row * NFEAT) + lid * 2;
        dst[0] = __nv_bfloat162(b0, b1);
        dst[1] = __nv_bfloat162(b2, b3);
        // quantized values downstream (diag exactly 0 -> out = 1)
        float fx = __bfloat162float(b0), fy = __bfloat162float(b1);
        float fz = __bfloat162float(b2), fw = __bfloat162float(b3);
        float sq = fx * fx + fy * fy + fz * fz + fw * fw;
        #pragma unroll
        for (int o = 16; o > 0; o >>= 1) sq += __shfl_xor_sync(0xFFFFFFFFu, sq, o);
        if (lid == 0) { g_norm[row] = sq; sn[wid] = sq; }
        ss[wid * NFEAT + lid * 4 + 0] = fx;
        ss[wid * NFEAT + lid * 4 + 1] = fy;
        ss[wid * NFEAT + lid * 4 + 2] = fz;
        ss[wid * NFEAT + lid * 4 + 3] = fw;
        __syncthreads();
        if (tid < NFEAT) {
            float t = 0.f;
            #pragma unroll
            for (int w = 0; w < 8; w++) t += ss[w * NFEAT + tid];
            g_s_part[b][tid] = t;
        }
        if (tid == 0) {
            float t = 0.f;
            #pragma unroll
            for (int w = 0; w < 8; w++) t += sn[w];
            g_sumn_part[b] = t;
        }
    }

    // =============== Device-wide barrier + sigma finalize ===============
    __threadfence();
    __syncthreads();
    if (tid == 0) s_last = (atomicAdd(&g_ctr, 1) == GRID - 1) ? 1 : 0;
    __syncthreads();

    if (s_last) {
        // all partials globally visible; high-MLP parallel reduction
        float* ssf = reinterpret_cast<float*>(smem + OFF_A);  // [2][128]
        {
            int f = tid & 127;
            int g = tid >> 7;
            float sf = 0.f;
            #pragma unroll 16
            for (int p = g * 128; p < g * 128 + 128; p++) sf += __ldcg(&g_s_part[p][f]);
            ssf[g * NFEAT + f] = sf;
        }
        if (tid < 32) {
            float sna = 0.f;
            #pragma unroll
            for (int q = 0; q < 8; q++) sna += __ldcg(&g_sumn_part[tid * 8 + q]);
            #pragma unroll
            for (int o = 16; o > 0; o >>= 1) sna += __shfl_xor_sync(0xFFFFFFFFu, sna, o);
            if (tid == 0) red[4] = sna;
        }
        __syncthreads();
        if (tid < NFEAT) {
            float s = ssf[tid] + ssf[NFEAT + tid];
            float v = s * s;
            #pragma unroll
            for (int o = 16; o > 0; o >>= 1) v += __shfl_xor_sync(0xFFFFFFFFu, v, o);
            if (lid == 0) red[wid] = v;
        }
        __syncthreads();
        if (tid == 0) {
            float S2   = red[0] + red[1] + red[2] + red[3];
            float sumn = red[4];
            float Nf = (float)NROWS;
            float inv2s = (Nf * Nf) / (4.f * Nf * sumn - 4.f * S2);
            g_c = inv2s * 1.4426950408889634f;   // fold log2(e) for ex2
            __threadfence();
            *((volatile int*)&g_flag) = 1;
        }
    }

    if (tid == 0) {
        volatile int* fp = &g_flag;
        while (*fp == 0) { __nanosleep(32); }
    }
    __syncthreads();

    float c = __ldcg(&g_c);

    // =============== Phase 3: GEMM tile + exp epilogue ===============
    int bj = b & 15;
    int bi = b >> 4;

    // constant tiles: ci = -ni*c, cj = -nj*c
    if (tid < TILE)
        reinterpret_cast<float*>(smem + OFF_CI)[tid] = -__ldcg(&g_norm[bi * TILE + tid]) * c;
    else
        reinterpret_cast<float*>(smem + OFF_CJ)[tid - TILE] =
            -__ldcg(&g_norm[bj * TILE + (tid - TILE)]) * c;

    // load A/B tiles into swizzled smem (ldcg: L2-coherent reads of phase-1 data)
    const uint4* A4 = reinterpret_cast<const uint4*>(g_Xb + (size_t)bi * TILE * NFEAT);
    const uint4* B4 = reinterpret_cast<const uint4*>(g_Xb + (size_t)bj * TILE * NFEAT);
    #pragma unroll
    for (int idx = tid; idx < 2048; idx += 256) {
        int row = idx >> 4;
        int ch  = idx & 15;
        uint32_t off = (uint32_t)row * 256u + (uint32_t)(ch ^ (row & 7)) * 16u;
        *reinterpret_cast<uint4*>(smem + OFF_A + off) = __ldcg(&A4[idx]);
        *reinterpret_cast<uint4*>(smem + OFF_B + off) = __ldcg(&B4[idx]);
    }
    __syncthreads();

    // per-warp MMA: warp computes rows wm..wm+31, cols wn..wn+63
    int wm = (wid & 3) * 32;
    int wn = (wid >> 2) * 64;

    float d[2][8][4];
    #pragma unroll
    for (int mt = 0; mt < 2; mt++)
        #pragma unroll
        for (int nt = 0; nt < 8; nt++)
            #pragma unroll
            for (int e = 0; e < 4; e++) d[mt][nt][e] = 0.f;

    uint32_t a_row  = (uint32_t)(wm + (lid & 15));
    uint32_t a_cbit = (uint32_t)(lid >> 4);
    uint32_t a_rl   = a_row & 7;
    uint32_t a_base0 = sb + OFF_A + a_row * 256u;
    uint32_t a_base1 = a_base0 + 16u * 256u;

    uint32_t b_row  = (uint32_t)(wn + (lid & 7) + ((lid & 16) >> 1));
    uint32_t b_cbit = (uint32_t)((lid >> 3) & 1);
    uint32_t b_rl   = b_row & 7;
    uint32_t b_base = sb + OFF_B + b_row * 256u;

    // double-buffered fragments: load kc+1 while issuing kc's MMAs
    uint32_t af[2][2][4];
    uint32_t bf[2][8][2];

#define LOAD_A(kc, bufi) do {                                                   \
        uint32_t sc = ((uint32_t)(2 * (kc)) + a_cbit) ^ a_rl;                   \
        ldmatrix_x4(af[bufi][0][0], af[bufi][0][1], af[bufi][0][2],             \
                    af[bufi][0][3], a_base0 + (sc << 4));                       \
        ldmatrix_x4(af[bufi][1][0], af[bufi][1][1], af[bufi][1][2],             \
                    af[bufi][1][3], a_base1 + (sc << 4));                       \
    } while (0)

#define LOAD_B(kc, bufi) do {                                                   \
        uint32_t sc = ((uint32_t)(2 * (kc)) + b_cbit) ^ b_rl;                   \
        _Pragma("unroll")                                                       \
        for (int p = 0; p < 4; p++) {                                           \
            uint32_t addr = b_base + (uint32_t)p * (16u * 256u) + (sc << 4);    \
            ldmatrix_x4(bf[bufi][2 * p][0], bf[bufi][2 * p][1],                 \
                        bf[bufi][2 * p + 1][0], bf[bufi][2 * p + 1][1], addr);  \
        }                                                                       \
    } while (0)

    LOAD_A(0, 0);
    LOAD_B(0, 0);
    #pragma unroll
    for (int kc = 0; kc < 8; kc++) {
        int cur = kc & 1, nxt = cur ^ 1;
        if (kc < 7) { LOAD_A(kc + 1, nxt); LOAD_B(kc + 1, nxt); }
        #pragma unroll
        for (int mt = 0; mt < 2; mt++)
            #pragma unroll
            for (int nt = 0; nt < 8; nt++)
                mma_16816(d[mt][nt], af[cur][mt], bf[cur][nt]);
    }
#undef LOAD_A
#undef LOAD_B

    // epilogue: out = ex2(dot * 2c + ci + cj)
    float sc2 = 2.f * c;
    const float* cis = reinterpret_cast<const float*>(smem + OFF_CI);
    const float* cjs = reinterpret_cast<const float*>(smem + OFF_CJ);
    int quad = lid >> 2;
    int qt   = lid & 3;

    #pragma unroll
    for (int mt = 0; mt < 2; mt++) {
        #pragma unroll
        for (int half = 0; half < 2; half++) {
            int r  = wm + mt * 16 + quad + half * 8;
            float ci = cis[r];
            float* orow = out + (size_t)(bi * TILE + r) * NROWS + (size_t)bj * TILE + wn;
            #pragma unroll
            for (int nt = 0; nt < 8; nt++) {
                int col = nt * 8 + qt * 2;
                float e0 = fmaf(d[mt][nt][half * 2 + 0], sc2, ci + cjs[wn + col]);
                float e1 = fmaf(d[mt][nt][half * 2 + 1], sc2, ci + cjs[wn + col + 1]);
                *reinterpret_cast<float2*>(orow + col) = make_float2(ex2f(e0), ex2f(e1));
            }
        }
    }

    // =============== reset counters for next graph replay ===============
    __syncthreads();
    if (tid == 0) {
        int a2 = atomicAdd(&g_ctr2, 1);
        if (a2 == GRID - 1) {          // everyone has passed the barrier
            g_ctr  = 0;
            g_ctr2 = 0;
            g_flag = 0;
        }
    }
}

// ---------------------------------------------------------------------------
// Launch
// ---------------------------------------------------------------------------
extern "C" void kernel_launch(void* const* d_in, const int* in_sizes, int n_in,
                              void* d_out, int out_size) {
    const float* X = (const float*)d_in[0];
    float* out = (float*)d_out;
    (void)in_sizes; (void)n_in; (void)out_size;

    cudaFuncSetAttribute(gauss_fused_kernel,
                         cudaFuncAttributeMaxDynamicSharedMemorySize, SMEM_TOTAL);

    gauss_fused_kernel<<<GRID, 256, SMEM_TOTAL>>>(X, out);
}

// round 6
// speedup vs baseline: 1.5981x; 1.0561x over previous
#include <cuda_runtime.h>
#include <cuda_bf16.h>
#include <cstdint>

// ---------------------------------------------------------------------------
// Problem constants
// ---------------------------------------------------------------------------
#define NROWS 2048
#define NFEAT 128
#define TILE  128
#define GRID  256                 // 16x16 tiles, one CTA each; all co-resident

// ---------------------------------------------------------------------------
// Device scratch (zero-initialized; no allocation allowed)
// ---------------------------------------------------------------------------
__device__ __nv_bfloat16 g_Xb[NROWS * NFEAT];   // bf16-quantized X
__device__ float g_norm[NROWS];                 // row norms of quantized X
__device__ float g_s_part[GRID][NFEAT];         // per-CTA feature-sum partials
__device__ float g_sumn_part[GRID];             // per-CTA sum-of-norms partials
__device__ float g_c;                           // inv2s * log2(e)
__device__ int   g_ctr;                         // phase-1 arrive counter
__device__ int   g_ctr2;                        // exit counter (for reset)
__device__ int   g_flag1;                       // phase-1 data visible
__device__ int   g_flag2;                       // sigma ready

// ---------------------------------------------------------------------------
// Helpers
// ---------------------------------------------------------------------------
__device__ __forceinline__ uint32_t smem_to_u32(const void* p) {
    uint32_t a;
    asm("{ .reg .u64 t; cvta.to.shared.u64 t, %1; cvt.u32.u64 %0, t; }" : "=r"(a) : "l"(p));
    return a;
}

__device__ __forceinline__ void ldmatrix_x4(uint32_t& r0, uint32_t& r1,
                                            uint32_t& r2, uint32_t& r3, uint32_t addr) {
    asm volatile("ldmatrix.sync.aligned.m8n8.x4.shared.b16 {%0,%1,%2,%3}, [%4];"
                 : "=r"(r0), "=r"(r1), "=r"(r2), "=r"(r3) : "r"(addr));
}

__device__ __forceinline__ void mma_16816(float* d, const uint32_t* a, const uint32_t* b) {
    asm volatile(
        "mma.sync.aligned.m16n8k16.row.col.f32.bf16.bf16.f32 "
        "{%0,%1,%2,%3}, {%4,%5,%6,%7}, {%8,%9}, {%0,%1,%2,%3};"
        : "+f"(d[0]), "+f"(d[1]), "+f"(d[2]), "+f"(d[3])
        : "r"(a[0]), "r"(a[1]), "r"(a[2]), "r"(a[3]), "r"(b[0]), "r"(b[1]));
}

__device__ __forceinline__ float ex2f(float x) {
    float r;
    asm("ex2.approx.ftz.f32 %0, %1;" : "=f"(r) : "f"(x));
    return r;
}

__device__ __forceinline__ void spin_until(volatile int* fp) {
    while (*fp == 0) { __nanosleep(32); }
}

// ---------------------------------------------------------------------------
// Smem layout (dynamic, 66560 B): ci/cj const tiles + A/B bf16 tiles.
// OFF_A region reused: phase-1 partials, finalize scratch, tiles.
// ---------------------------------------------------------------------------
#define OFF_CI  0
#define OFF_CJ  512
#define OFF_A   1024
#define OFF_B   (1024 + 32768)
#define SMEM_TOTAL (OFF_B + 32768)

// ---------------------------------------------------------------------------
// ONE fused kernel. sigma finalize runs CONCURRENTLY with everyone's MMA:
//   flag1 (data visible) gates tile loads; flag2 (sigma) gates only epilogue.
// ---------------------------------------------------------------------------
__global__ void __launch_bounds__(256, 2) gauss_fused_kernel(
        const float* __restrict__ X, float* __restrict__ out) {
    extern __shared__ char smem[];
    uint32_t sb = smem_to_u32(smem);
    int b   = blockIdx.x;
    int tid = threadIdx.x;
    int wid = tid >> 5;
    int lid = tid & 31;

    __shared__ float sn[8];
    __shared__ float red[5];
    __shared__ int   s_last;

    // =============== Phase 1: quantize 8 rows, partials ===============
    {
        float* ss = reinterpret_cast<float*>(smem + OFF_A);   // [8][128]
        int row = b * 8 + wid;                                // warp owns one row
        float4 v = reinterpret_cast<const float4*>(X + (size_t)row * NFEAT)[lid];
        __nv_bfloat16 b0 = __float2bfloat16(v.x);
        __nv_bfloat16 b1 = __float2bfloat16(v.y);
        __nv_bfloat16 b2 = __float2bfloat16(v.z);
        __nv_bfloat16 b3 = __float2bfloat16(v.w);
        __nv_bfloat162* dst =
            reinterpret_cast<__nv_bfloat162*>(g_Xb + (size_t)row * NFEAT) + lid * 2;
        dst[0] = __nv_bfloat162(b0, b1);
        dst[1] = __nv_bfloat162(b2, b3);
        // quantized values downstream (diag exactly 0 -> out = 1)
        float fx = __bfloat162float(b0), fy = __bfloat162float(b1);
        float fz = __bfloat162float(b2), fw = __bfloat162float(b3);
        float sq = fx * fx + fy * fy + fz * fz + fw * fw;
        #pragma unroll
        for (int o = 16; o > 0; o >>= 1) sq += __shfl_xor_sync(0xFFFFFFFFu, sq, o);
        if (lid == 0) { g_norm[row] = sq; sn[wid] = sq; }
        ss[wid * NFEAT + lid * 4 + 0] = fx;
        ss[wid * NFEAT + lid * 4 + 1] = fy;
        ss[wid * NFEAT + lid * 4 + 2] = fz;
        ss[wid * NFEAT + lid * 4 + 3] = fw;
        __syncthreads();
        if (tid < NFEAT) {
            float t = 0.f;
            #pragma unroll
            for (int w = 0; w < 8; w++) t += ss[w * NFEAT + tid];
            g_s_part[b][tid] = t;
        }
        if (tid == 0) {
            float t = 0.f;
            #pragma unroll
            for (int w = 0; w < 8; w++) t += sn[w];
            g_sumn_part[b] = t;
        }
    }

    // =============== Barrier: release flag1 immediately ===============
    __threadfence();
    __syncthreads();
    if (tid == 0) {
        int last = (atomicAdd(&g_ctr, 1) == GRID - 1) ? 1 : 0;
        s_last = last;
        if (last) *((volatile int*)&g_flag1) = 1;   // data visible -> everyone go
        else spin_until(&g_flag1);
    }
    __syncthreads();

    // =============== Last CTA: sigma finalize (concurrent with MMA) ========
    if (s_last) {
        float* ssf = reinterpret_cast<float*>(smem + OFF_A);  // [2][128]
        {
            int f = tid & 127;
            int g = tid >> 7;
            float sf = 0.f;
            #pragma unroll 16
            for (int p = g * 128; p < g * 128 + 128; p++) sf += __ldcg(&g_s_part[p][f]);
            ssf[g * NFEAT + f] = sf;
        }
        if (tid < 32) {
            float sna = 0.f;
            #pragma unroll
            for (int q = 0; q < 8; q++) sna += __ldcg(&g_sumn_part[tid * 8 + q]);
            #pragma unroll
            for (int o = 16; o > 0; o >>= 1) sna += __shfl_xor_sync(0xFFFFFFFFu, sna, o);
            if (tid == 0) red[4] = sna;
        }
        __syncthreads();
        if (tid < NFEAT) {
            float s = ssf[tid] + ssf[NFEAT + tid];
            float v = s * s;
            #pragma unroll
            for (int o = 16; o > 0; o >>= 1) v += __shfl_xor_sync(0xFFFFFFFFu, v, o);
            if (lid == 0) red[wid] = v;
        }
        __syncthreads();
        if (tid == 0) {
            float S2   = red[0] + red[1] + red[2] + red[3];
            float sumn = red[4];
            float Nf = (float)NROWS;
            float inv2s = (Nf * Nf) / (4.f * Nf * sumn - 4.f * S2);
            g_c = inv2s * 1.4426950408889634f;   // fold log2(e) for ex2
            __threadfence();
            *((volatile int*)&g_flag2) = 1;
        }
        __syncthreads();   // smem OFF_A about to be reused for tiles
    }

    // =============== Phase 3: GEMM tile (sigma NOT needed yet) ===========
    int bj = b & 15;
    int bi = b >> 4;

    // prefetch raw norms (visible since flag1): tid<128 -> ni, else nj
    float n_pref = (tid < TILE)
        ? __ldcg(&g_norm[bi * TILE + tid])
        : __ldcg(&g_norm[bj * TILE + (tid - TILE)]);

    // load A/B tiles into swizzled smem (L2-coherent reads of phase-1 data)
    const uint4* A4 = reinterpret_cast<const uint4*>(g_Xb + (size_t)bi * TILE * NFEAT);
    const uint4* B4 = reinterpret_cast<const uint4*>(g_Xb + (size_t)bj * TILE * NFEAT);
    #pragma unroll
    for (int idx = tid; idx < 2048; idx += 256) {
        int row = idx >> 4;
        int ch  = idx & 15;
        uint32_t off = (uint32_t)row * 256u + (uint32_t)(ch ^ (row & 7)) * 16u;
        *reinterpret_cast<uint4*>(smem + OFF_A + off) = __ldcg(&A4[idx]);
        *reinterpret_cast<uint4*>(smem + OFF_B + off) = __ldcg(&B4[idx]);
    }
    __syncthreads();

    // per-warp MMA: warp computes rows wm..wm+31, cols wn..wn+63
    int wm = (wid & 3) * 32;
    int wn = (wid >> 2) * 64;

    float d[2][8][4];
    #pragma unroll
    for (int mt = 0; mt < 2; mt++)
        #pragma unroll
        for (int nt = 0; nt < 8; nt++)
            #pragma unroll
            for (int e = 0; e < 4; e++) d[mt][nt][e] = 0.f;

    uint32_t a_row  = (uint32_t)(wm + (lid & 15));
    uint32_t a_cbit = (uint32_t)(lid >> 4);
    uint32_t a_rl   = a_row & 7;
    uint32_t a_base0 = sb + OFF_A + a_row * 256u;
    uint32_t a_base1 = a_base0 + 16u * 256u;

    uint32_t b_row  = (uint32_t)(wn + (lid & 7) + ((lid & 16) >> 1));
    uint32_t b_cbit = (uint32_t)((lid >> 3) & 1);
    uint32_t b_rl   = b_row & 7;
    uint32_t b_base = sb + OFF_B + b_row * 256u;

    // double-buffered fragments: load kc+1 while issuing kc's MMAs
    uint32_t af[2][2][4];
    uint32_t bf[2][8][2];

#define LOAD_A(kc, bufi) do {                                                   \
        uint32_t sc = ((uint32_t)(2 * (kc)) + a_cbit) ^ a_rl;                   \
        ldmatrix_x4(af[bufi][0][0], af[bufi][0][1], af[bufi][0][2],             \
                    af[bufi][0][3], a_base0 + (sc << 4));                       \
        ldmatrix_x4(af[bufi][1][0], af[bufi][1][1], af[bufi][1][2],             \
                    af[bufi][1][3], a_base1 + (sc << 4));                       \
    } while (0)

#define LOAD_B(kc, bufi) do {                                                   \
        uint32_t sc = ((uint32_t)(2 * (kc)) + b_cbit) ^ b_rl;                   \
        _Pragma("unroll")                                                       \
        for (int p = 0; p < 4; p++) {                                           \
            uint32_t addr = b_base + (uint32_t)p * (16u * 256u) + (sc << 4);    \
            ldmatrix_x4(bf[bufi][2 * p][0], bf[bufi][2 * p][1],                 \
                        bf[bufi][2 * p + 1][0], bf[bufi][2 * p + 1][1], addr);  \
        }                                                                       \
    } while (0)

    LOAD_A(0, 0);
    LOAD_B(0, 0);
    #pragma unroll
    for (int kc = 0; kc < 8; kc++) {
        int cur = kc & 1, nxt = cur ^ 1;
        if (kc < 7) { LOAD_A(kc + 1, nxt); LOAD_B(kc + 1, nxt); }
        #pragma unroll
        for (int mt = 0; mt < 2; mt++)
            #pragma unroll
            for (int nt = 0; nt < 8; nt++)
                mma_16816(d[mt][nt], af[cur][mt], bf[cur][nt]);
    }
#undef LOAD_A
#undef LOAD_B

    // =============== Wait for sigma (already done for most CTAs) =========
    if (tid == 0) spin_until(&g_flag2);
    __syncthreads();
    float c = __ldcg(&g_c);

    // write const tiles: ci = -ni*c, cj = -nj*c
    if (tid < TILE)
        reinterpret_cast<float*>(smem + OFF_CI)[tid] = -n_pref * c;
    else
        reinterpret_cast<float*>(smem + OFF_CJ)[tid - TILE] = -n_pref * c;
    __syncthreads();

    // epilogue: out = ex2(dot * 2c + ci + cj)
    float sc2 = 2.f * c;
    const float* cis = reinterpret_cast<const float*>(smem + OFF_CI);
    const float* cjs = reinterpret_cast<const float*>(smem + OFF_CJ);
    int quad = lid >> 2;
    int qt   = lid & 3;

    #pragma unroll
    for (int mt = 0; mt < 2; mt++) {
        #pragma unroll
        for (int half = 0; half < 2; half++) {
            int r  = wm + mt * 16 + quad + half * 8;
            float ci = cis[r];
            float* orow = out + (size_t)(bi * TILE + r) * NROWS + (size_t)bj * TILE + wn;
            #pragma unroll
            for (int nt = 0; nt < 8; nt++) {
                int col = nt * 8 + qt * 2;
                float e0 = fmaf(d[mt][nt][half * 2 + 0], sc2, ci + cjs[wn + col]);
                float e1 = fmaf(d[mt][nt][half * 2 + 1], sc2, ci + cjs[wn + col + 1]);
                *reinterpret_cast<float2*>(orow + col) = make_float2(ex2f(e0), ex2f(e1));
            }
        }
    }

    // =============== reset counters for next graph replay ===============
    __syncthreads();
    if (tid == 0) {
        int a2 = atomicAdd(&g_ctr2, 1);
        if (a2 == GRID - 1) {          // everyone has passed both flags
            g_ctr   = 0;
            g_ctr2  = 0;
            g_flag1 = 0;
            g_flag2 = 0;
        }
    }
}

// ---------------------------------------------------------------------------
// Launch
// ---------------------------------------------------------------------------
extern "C" void kernel_launch(void* const* d_in, const int* in_sizes, int n_in,
                              void* d_out, int out_size) {
    const float* X = (const float*)d_in[0];
    float* out = (float*)d_out;
    (void)in_sizes; (void)n_in; (void)out_size;

    cudaFuncSetAttribute(gauss_fused_kernel,
                         cudaFuncAttributeMaxDynamicSharedMemorySize, SMEM_TOTAL);

    gauss_fused_kernel<<<GRID, 256, SMEM_TOTAL>>>(X, out);
}